// round 1
// baseline (speedup 1.0000x reference)
#include <cuda_runtime.h>
#include <cstdint>

// Problem constants
#define S_SEG 8
#define U_CH 128
#define SU 1024            // S_SEG * U_CH
#define P_MAX 64
#define ZPB 8              // z per block (1 warp per z)
#define NTHREADS 256       // ZPB * 32

// Preprocessed path metadata (written by prep kernel each launch)
__device__ uint4 g_meta[P_MAX];   // {off0_bytes, off1_bytes, off2_bytes, coeff_bits} sorted by i3
__device__ int   g_start[S_SEG + 1];

__global__ void prep_kernel(const int* __restrict__ path_indices,
                            const float* __restrict__ path_coeff,
                            int P) {
    if (threadIdx.x != 0 || blockIdx.x != 0) return;
    int cnt[S_SEG];
    for (int j = 0; j < S_SEG; j++) cnt[j] = 0;
    for (int p = 0; p < P; p++) cnt[path_indices[p * 4 + 3]]++;
    int st[S_SEG + 1];
    st[0] = 0;
    for (int j = 0; j < S_SEG; j++) st[j + 1] = st[j] + cnt[j];
    for (int j = 0; j <= S_SEG; j++) g_start[j] = st[j];
    int pos[S_SEG];
    for (int j = 0; j < S_SEG; j++) pos[j] = st[j];
    for (int p = 0; p < P; p++) {
        int i0 = path_indices[p * 4 + 0];
        int i1 = path_indices[p * 4 + 1];
        int i2 = path_indices[p * 4 + 2];
        int i3 = path_indices[p * 4 + 3];
        uint4 m;
        // byte offsets into the per-z shared tile: [src*8 + seg] * 128 floats * 4B
        m.x = (unsigned)((0 * S_SEG + i0) * U_CH * 4);
        m.y = (unsigned)((1 * S_SEG + i1) * U_CH * 4);
        m.z = (unsigned)((2 * S_SEG + i2) * U_CH * 4);
        m.w = __float_as_uint(path_coeff[p]);
        g_meta[pos[i3]++] = m;
    }
}

__device__ __forceinline__ unsigned smem_u32(const void* p) {
    unsigned a;
    asm("{ .reg .u64 t; cvta.to.shared.u64 t, %1; cvt.u32.u64 %0, t; }"
        : "=r"(a) : "l"(p));
    return a;
}

__device__ __forceinline__ void lds128(unsigned long long& a0, unsigned long long& a1,
                                       unsigned addr) {
    asm volatile("ld.shared.v2.u64 {%0, %1}, [%2];"
                 : "=l"(a0), "=l"(a1) : "r"(addr));
}

__device__ __forceinline__ unsigned long long mul2(unsigned long long a, unsigned long long b) {
    unsigned long long r;
    asm("mul.rn.f32x2 %0, %1, %2;" : "=l"(r) : "l"(a), "l"(b));
    return r;
}

__device__ __forceinline__ unsigned long long fma2(unsigned long long a, unsigned long long b,
                                                   unsigned long long c) {
    unsigned long long r;
    asm("fma.rn.f32x2 %0, %1, %2, %3;" : "=l"(r) : "l"(a), "l"(b), "l"(c));
    return r;
}

__global__ __launch_bounds__(NTHREADS, 2)
void ftp4_kernel(const float* __restrict__ x0,
                 const float* __restrict__ x1,
                 const float* __restrict__ x2,
                 float* __restrict__ out,
                 int Z) {
    extern __shared__ float smem[];
    // layout: [ZPB][3*S_SEG][U_CH] floats, then meta (64 x uint4), then starts (9 ints)
    uint4* smeta = (uint4*)(smem + ZPB * 3 * S_SEG * U_CH);
    int*   sstart = (int*)(smeta + P_MAX);

    const int tid = threadIdx.x;
    if (tid < P_MAX) smeta[tid] = g_meta[tid];
    if (tid < S_SEG + 1) sstart[tid] = g_start[tid];

    const int w = tid >> 5;       // z_local (0..7)
    const int lane = tid & 31;    // owns u4 = lane (float4 over u)
    const long z = (long)blockIdx.x * ZPB + w;
    const bool active = (z < Z);

    float* sz = smem + w * (3 * S_SEG * U_CH);

    if (active) {
        const float4* p0 = (const float4*)(x0 + z * SU);
        const float4* p1 = (const float4*)(x1 + z * SU);
        const float4* p2 = (const float4*)(x2 + z * SU);
        float4* s4 = (float4*)sz;
#pragma unroll
        for (int s = 0; s < S_SEG; s++)
            s4[(0 * S_SEG + s) * 32 + lane] = p0[s * 32 + lane];
#pragma unroll
        for (int s = 0; s < S_SEG; s++)
            s4[(1 * S_SEG + s) * 32 + lane] = p1[s * 32 + lane];
#pragma unroll
        for (int s = 0; s < S_SEG; s++)
            s4[(2 * S_SEG + s) * 32 + lane] = p2[s * 32 + lane];
    }
    __syncthreads();

    if (!active) return;

    const unsigned sbase = smem_u32(sz) + lane * 16;

#pragma unroll
    for (int j = 0; j < S_SEG; j++) {
        unsigned long long acc0 = 0ull, acc1 = 0ull;
        const int pb = sstart[j];
        const int pe = sstart[j + 1];
        for (int p = pb; p < pe; ++p) {
            uint4 m = smeta[p];
            unsigned long long a0, a1, b0, b1, c0, c1;
            lds128(a0, a1, sbase + m.x);
            lds128(b0, b1, sbase + m.y);
            lds128(c0, c1, sbase + m.z);
            unsigned long long cc;
            asm("mov.b64 %0, {%1, %1};" : "=l"(cc) : "r"(m.w));
            unsigned long long t0 = mul2(a0, b0);
            unsigned long long t1 = mul2(a1, b1);
            t0 = mul2(t0, c0);
            t1 = mul2(t1, c1);
            acc0 = fma2(t0, cc, acc0);
            acc1 = fma2(t1, cc, acc1);
        }
        float4 r;
        unsigned r0, r1, r2, r3;
        asm("mov.b64 {%0, %1}, %2;" : "=r"(r0), "=r"(r1) : "l"(acc0));
        asm("mov.b64 {%0, %1}, %2;" : "=r"(r2), "=r"(r3) : "l"(acc1));
        r.x = __uint_as_float(r0);
        r.y = __uint_as_float(r1);
        r.z = __uint_as_float(r2);
        r.w = __uint_as_float(r3);
        *(float4*)(out + z * SU + j * U_CH + lane * 4) = r;
    }
}

extern "C" void kernel_launch(void* const* d_in, const int* in_sizes, int n_in,
                              void* d_out, int out_size) {
    const float* x0 = (const float*)d_in[0];
    const float* x1 = (const float*)d_in[1];
    const float* x2 = (const float*)d_in[2];
    const float* coeff = (const float*)d_in[3];
    const int*   pidx = (const int*)d_in[4];
    float* out = (float*)d_out;

    const int P = in_sizes[3];            // 64
    const int Z = in_sizes[0] / SU;       // 20000

    prep_kernel<<<1, 32>>>(pidx, coeff, P);

    const size_t smem_bytes =
        (size_t)ZPB * 3 * S_SEG * U_CH * sizeof(float) +
        P_MAX * sizeof(uint4) + (S_SEG + 1) * sizeof(int);

    static bool attr_set = false;
    if (!attr_set) {
        cudaFuncSetAttribute(ftp4_kernel,
                             cudaFuncAttributeMaxDynamicSharedMemorySize,
                             (int)smem_bytes);
        attr_set = true;
    }

    const int grid = (Z + ZPB - 1) / ZPB;
    ftp4_kernel<<<grid, NTHREADS, smem_bytes>>>(x0, x1, x2, out, Z);
}